// round 1
// baseline (speedup 1.0000x reference)
#include <cuda_runtime.h>

// ItemEncoder: out[b,l,:] = M[ids[b,l], :] @ W^T + b
//   ids: int32 [64*200]=12800, M: fp32 [100000,2000], W: fp32 [8,2000], b: fp32 [8]
//   out: fp32 [12800, 8]
//
// Strategy: warp processes 4 tokens at a time (one "group"; 3200 groups).
// Each lane handles one 16B quad (4 floats) of the 2000-dim rows per iteration:
//   - 4 row loads (LDG.128, DRAM-bound gather)
//   - 8 W loads  (LDG.128, L1-resident after warmup; amortized over 4 tokens)
//   - 64 packed fma.rn.f32x2 (Blackwell f32x2 pipe, halves FFMA count)
// Epilogue: butterfly transpose-reduce so lane l ends with output g*32+l
// -> one coalesced 128B STG per group.

static constexpr int D    = 2000;   // input dim
static constexpr int D4   = D / 4;  // 500 16B-quads per row
static constexpr int GROUPS = 3200; // 12800 tokens / 4

__device__ __forceinline__ void ffma2(unsigned long long &acc,
                                      unsigned long long a,
                                      unsigned long long b) {
    asm("fma.rn.f32x2 %0, %1, %2, %0;" : "+l"(acc) : "l"(a), "l"(b));
}

__device__ __forceinline__ void accum_quad(
    int q,
    const ulonglong2* __restrict__ r0, const ulonglong2* __restrict__ r1,
    const ulonglong2* __restrict__ r2, const ulonglong2* __restrict__ r3,
    const ulonglong2* __restrict__ wb,
    unsigned long long (&acc)[4][8])
{
    // Row data first (independent DRAM loads -> MLP)
    ulonglong2 v[4];
    v[0] = __ldg(r0 + q);
    v[1] = __ldg(r1 + q);
    v[2] = __ldg(r2 + q);
    v[3] = __ldg(r3 + q);

    ulonglong2 w[8];
#pragma unroll
    for (int o = 0; o < 8; ++o)
        w[o] = __ldg(wb + o * D4 + q);

#pragma unroll
    for (int t = 0; t < 4; ++t) {
#pragma unroll
        for (int o = 0; o < 8; ++o) {
            ffma2(acc[t][o], v[t].x, w[o].x);
            ffma2(acc[t][o], v[t].y, w[o].y);
        }
    }
}

__global__ void __launch_bounds__(256, 2)
gather_proj_kernel(const int*   __restrict__ ids,
                   const float* __restrict__ M,
                   const float* __restrict__ W,
                   const float* __restrict__ bias,
                   float*       __restrict__ out)
{
    const int lane   = threadIdx.x & 31;
    const int gwarp  = (blockIdx.x * blockDim.x + threadIdx.x) >> 5;
    const int nwarps = (gridDim.x * blockDim.x) >> 5;

    const float bval = __ldg(bias + (lane & 7));
    const ulonglong2* wb = (const ulonglong2*)W;

    for (int g = gwarp; g < GROUPS; g += nwarps) {
        // 4 token ids for this group (16B-aligned: g*4 ints)
        const int4 ii = __ldg((const int4*)ids + g);
        const ulonglong2* r0 = (const ulonglong2*)M + (size_t)ii.x * D4;
        const ulonglong2* r1 = (const ulonglong2*)M + (size_t)ii.y * D4;
        const ulonglong2* r2 = (const ulonglong2*)M + (size_t)ii.z * D4;
        const ulonglong2* r3 = (const ulonglong2*)M + (size_t)ii.w * D4;

        unsigned long long acc[4][8];
#pragma unroll
        for (int t = 0; t < 4; ++t)
#pragma unroll
            for (int o = 0; o < 8; ++o)
                acc[t][o] = 0ULL;

        // 500 quads: 15 full warp-iterations + 20-lane tail
#pragma unroll 5
        for (int it = 0; it < 15; ++it) {
            const int q = it * 32 + lane;
            accum_quad(q, r0, r1, r2, r3, wb, acc);
        }
        if (lane < 20) {
            accum_quad(480 + lane, r0, r1, r2, r3, wb, acc);
        }

        // Collapse f32x2 halves -> 32 scalar partials per lane
        float cur[32];
#pragma unroll
        for (int t = 0; t < 4; ++t)
#pragma unroll
            for (int o = 0; o < 8; ++o) {
                const unsigned long long a = acc[t][o];
                cur[t * 8 + o] = __uint_as_float((unsigned)a) +
                                 __uint_as_float((unsigned)(a >> 32));
            }

        // Butterfly transpose-reduce: lane l ends with total of value index l.
        // 31 shuffles total (vs 160 for naive per-value allreduce).
#pragma unroll
        for (int off = 16; off >= 1; off >>= 1) {
            const bool up = (lane & off) != 0;
#pragma unroll
            for (int j = 0; j < off; ++j) {
                float keep = up ? cur[j + off] : cur[j];
                float give = up ? cur[j] : cur[j + off];
                keep += __shfl_xor_sync(0xffffffffu, give, off);
                cur[j] = keep;
            }
        }

        // value index l = (token t = l>>3, out o = l&7) -> out[(4g + t)*8 + o] = out[g*32 + l]
        out[(size_t)g * 32 + lane] = cur[0] + bval;
    }
}

extern "C" void kernel_launch(void* const* d_in, const int* in_sizes, int n_in,
                              void* d_out, int out_size) {
    const int*   ids  = (const int*)  d_in[0];
    const float* M    = (const float*)d_in[1];
    const float* W    = (const float*)d_in[2];
    const float* bias = (const float*)d_in[3];
    float*       out  = (float*)d_out;

    // 304 CTAs = 2 per SM (152 SMs on GB300), 8 warps each -> 2432 warps
    // over 3200 groups (768 warps take a second group).
    gather_proj_kernel<<<304, 256>>>(ids, M, W, bias, out);
}

// round 2
// speedup vs baseline: 1.1400x; 1.1400x over previous
#include <cuda_runtime.h>
#include <cstdint>

// ItemEncoder: out[t,:] = M[ids[t],:] @ W^T + b  for 12800 tokens, D=2000, O=8.
//
// Pipeline design (GB300 / sm_103a):
//  - 1 CTA per SM (grid = #SMs), 256 threads.
//  - W (64 KB) staged to smem once per CTA.
//  - Rows gathered in stages of 8 tokens (64 KB) via cp.async.cg (LDGSTS,
//    register-free MLP), double buffered.
//  - Compute: warps 0-3 handle stage tokens 0-3, warps 4-7 tokens 4-7;
//    each warp covers a quarter of the 500 row-quads, fp32x2 FMAs,
//    butterfly transpose-reduce, cross-warp sum via smem, coalesced store.

static constexpr int NTOK   = 12800;
static constexpr int D      = 2000;
static constexpr int ROWB   = D * 4;          // 8000 bytes per row
static constexpr int QPR    = D / 4;          // 500 quads per row
static constexpr int STOK   = 8;              // tokens per stage
static constexpr int NSTG   = NTOK / STOK;    // 1600 stages
static constexpr int SQUADS = STOK * QPR;     // 4000 quads per stage
static constexpr int NTHR   = 256;

// smem byte offsets
static constexpr int SM_W   = 0;                   // 64000 B
static constexpr int SM_S0  = 64000;               // 64000 B
static constexpr int SM_S1  = 128000;              // 64000 B
static constexpr int SM_RED = 192000;              // 8*32*4 = 1024 B
static constexpr int SM_TOT = 193024;

__device__ __forceinline__ void ffma2(unsigned long long &acc,
                                      unsigned long long a,
                                      unsigned long long b) {
    asm("fma.rn.f32x2 %0, %1, %2, %0;" : "+l"(acc) : "l"(a), "l"(b));
}

__device__ __forceinline__ void cp16(void* smem_dst, const void* gmem_src) {
    unsigned s = (unsigned)__cvta_generic_to_shared(smem_dst);
    asm volatile("cp.async.cg.shared.global [%0], [%1], 16;\n"
                 :: "r"(s), "l"(gmem_src));
}
__device__ __forceinline__ void cp_commit() {
    asm volatile("cp.async.commit_group;\n" ::: "memory");
}
__device__ __forceinline__ void cp_wait1() {
    asm volatile("cp.async.wait_group 1;\n" ::: "memory");
}

// Issue cp.async for one stage of 8 gathered rows into dst.
__device__ __forceinline__ void issue_stage(char* dst, const int* __restrict__ ids,
                                            const char* __restrict__ Mb,
                                            int tok_base, int tid) {
#pragma unroll
    for (int k = 0; k < 16; ++k) {
        int j = tid + k * NTHR;
        if (k < 15 || j < SQUADS) {
            int r = (int)(((unsigned long long)(unsigned)j * 8389ull) >> 22); // j/500
            int c = j - r * 500;
            int row = __ldg(ids + tok_base + r);
            cp16(dst + r * ROWB + c * 16,
                 Mb + (size_t)row * ROWB + (size_t)c * 16);
        }
    }
}

__global__ void __launch_bounds__(NTHR, 1)
gather_proj_pipe(const int*   __restrict__ ids,
                 const float* __restrict__ M,
                 const float* __restrict__ W,
                 const float* __restrict__ bias,
                 float*       __restrict__ out)
{
    extern __shared__ char smem[];
    const int tid  = threadIdx.x;
    const int lane = tid & 31;
    const int wid  = tid >> 5;
    const int gid  = wid >> 2;   // token-group within stage (0 or 1)
    const int wig  = wid & 3;    // warp within group: quad-range owner

    const char* Mb = (const char*)M;
    const float bval = __ldg(bias + (lane & 7));

    // ---- prologue: W -> smem, prefetch first two local stages ----
    {
        const char* Wb = (const char*)W;
#pragma unroll
        for (int k = 0; k < 16; ++k) {
            int j = tid + k * NTHR;
            if (k < 15 || j < SQUADS)   // 4000 quads = 64000 B
                cp16(smem + SM_W + j * 16, Wb + j * 16);
        }
    }
    const int grid   = gridDim.x;
    const int s0     = blockIdx.x;
    const int nLocal = (NSTG - s0 + grid - 1) / grid;   // grid << 1600, so >=1

    issue_stage(smem + SM_S0, ids, Mb, s0 * STOK, tid);
    cp_commit();                                        // G0 = W + stage0
    if (nLocal > 1)
        issue_stage(smem + SM_S1, ids, Mb, (s0 + grid) * STOK, tid);
    cp_commit();                                        // G1 = stage1 (maybe empty)

    float* red = (float*)(smem + SM_RED);

    for (int k = 0; k < nLocal; ++k) {
        cp_wait1();            // stage k (and W) complete; stage k+1 may be in flight
        __syncthreads();       // (A) all threads see stage k; red[] readers done

        const int  tb  = (s0 + k * grid) * STOK;
        char* buf = smem + ((k & 1) ? SM_S1 : SM_S0);

        // ---- accumulate: this warp covers quads q = it*128 + wig*32 + lane ----
        unsigned long long acc[4][8];
#pragma unroll
        for (int t = 0; t < 4; ++t)
#pragma unroll
            for (int o = 0; o < 8; ++o) acc[t][o] = 0ull;

#pragma unroll
        for (int it = 0; it < 4; ++it) {
            const int q = it * 128 + wig * 32 + lane;
            if (q < QPR) {
                ulonglong2 v[4];
#pragma unroll
                for (int t = 0; t < 4; ++t)
                    v[t] = *(const ulonglong2*)(buf + (gid * 4 + t) * ROWB + q * 16);
                ulonglong2 w[8];
#pragma unroll
                for (int o = 0; o < 8; ++o)
                    w[o] = *(const ulonglong2*)(smem + SM_W + o * ROWB + q * 16);
#pragma unroll
                for (int t = 0; t < 4; ++t)
#pragma unroll
                    for (int o = 0; o < 8; ++o) {
                        ffma2(acc[t][o], v[t].x, w[o].x);
                        ffma2(acc[t][o], v[t].y, w[o].y);
                    }
            }
        }

        // ---- collapse f32x2 halves, butterfly transpose-reduce (31 shuffles) ----
        float cur[32];
#pragma unroll
        for (int t = 0; t < 4; ++t)
#pragma unroll
            for (int o = 0; o < 8; ++o) {
                const unsigned long long a = acc[t][o];
                cur[t * 8 + o] = __uint_as_float((unsigned)a) +
                                 __uint_as_float((unsigned)(a >> 32));
            }
#pragma unroll
        for (int off = 16; off >= 1; off >>= 1) {
            const bool up = (lane & off) != 0;
#pragma unroll
            for (int j = 0; j < off; ++j) {
                float keep = up ? cur[j + off] : cur[j];
                float give = up ? cur[j] : cur[j + off];
                keep += __shfl_xor_sync(0xffffffffu, give, off);
                cur[j] = keep;
            }
        }
        // lane now holds partial of output value (token gid*4 + (lane>>3), out lane&7)
        red[wid * 32 + lane] = cur[0];
        __syncthreads();       // (B) red[] visible; all warps done reading buf

        if (wig == 0) {        // warps 0 and 4 finalize their group's 32 outputs
            const int base = gid * 128;  // 4 warps * 32
            float s = red[base + lane] + red[base + 32 + lane] +
                      red[base + 64 + lane] + red[base + 96 + lane] + bval;
            out[(size_t)tb * 8 + gid * 32 + lane] = s;
        }

        // prefetch stage k+2 into the buffer just freed by barrier (B)
        if (k + 2 < nLocal)
            issue_stage(buf, ids, Mb, (s0 + (k + 2) * grid) * STOK, tid);
        cp_commit();           // commit every iter to keep wait_group math uniform
    }
}

extern "C" void kernel_launch(void* const* d_in, const int* in_sizes, int n_in,
                              void* d_out, int out_size) {
    const int*   ids  = (const int*)  d_in[0];
    const float* M    = (const float*)d_in[1];
    const float* W    = (const float*)d_in[2];
    const float* bias = (const float*)d_in[3];
    float*       out  = (float*)d_out;

    static_assert(SM_TOT <= 227 * 1024, "smem budget");
    cudaFuncSetAttribute(gather_proj_pipe,
                         cudaFuncAttributeMaxDynamicSharedMemorySize, SM_TOT);

    int nsm = 148;
    cudaDeviceGetAttribute(&nsm, cudaDevAttrMultiProcessorCount, 0);

    gather_proj_pipe<<<nsm, NTHR, SM_TOT>>>(ids, M, W, bias, out);
}